// round 10
// baseline (speedup 1.0000x reference)
#include <cuda_runtime.h>
#include <cuda_bf16.h>
#include <cstdint>

#define BINS 20
#define NODES 21
#define NWARPS 8
#define THREADS 256
#define MAXBLOCKS 592
#define STAGES 4
#define SLOTS (2 * BINS)
#define FRAC_BITS 13
#define FRAC_MASK ((1u << FRAC_BITS) - 1u)
#define INV_FRAC_SCALE (1.0f/8192.0f)
#define CNT_SHIFT 20                /* smem u32 pack: cnt<<20 | frac13 */
#define PACK_SCALE 163840.0f        /* BINS << FRAC_BITS = 20*8192 */
#define MAGIC 12582912.0f           /* 1.5 * 2^23: float->fixed trick */
#define MAGIC_BITS 0x4B400000u
#define TOT_SHIFT 36                /* global u64 pack: cnt<<36 | frac_sum */

// Packed totals + group-1 count. Static-zero at load; last block re-zeroes
// every launch so graph replays are deterministic.
__device__ unsigned long long g_tot[SLOTS];
__device__ unsigned int g_cnt1;
__device__ unsigned int g_done;

__device__ __forceinline__ void cpa16(uint32_t dst_smem, const void* src) {
    asm volatile("cp.async.cg.shared.global [%0], [%1], 16;"
                 :: "r"(dst_smem), "l"(src));
}
__device__ __forceinline__ void cpa_commit() {
    asm volatile("cp.async.commit_group;");
}
template <int N>
__device__ __forceinline__ void cpa_wait() {
    asm volatile("cp.async.wait_group %0;" :: "n"(N));
}

__device__ __forceinline__ void hx_accum(unsigned int* my, float x, int g,
                                         unsigned int lo, unsigned int span,
                                         unsigned int& c1) {
    // Float->fixed via FFMA magic: t = x*163840 + 1.5*2^23 lands in the
    // [2^23,2^24) binade (ulp=1), so bits(t)-MAGIC_BITS == rn(x*163840).
    // RN vs floor only shifts boundary elements continuously between
    // adjacent nodes (triangular kernel is continuous) -> loss unchanged.
    unsigned int u = __float_as_uint(fmaf(x, PACK_SCALE, MAGIC)) - MAGIC_BITS;
    unsigned int k = u >> FRAC_BITS;
    c1 += (unsigned int)g;                                  // exact group count
    if (k - lo <= span) {   // single unsigned compare: lo <= k <= hi
        unsigned int pk = (u & FRAC_MASK) | (1u << CNT_SHIFT);
        atomicAdd(&my[g * BINS + k], pk);
    }
}

__global__ __launch_bounds__(THREADS, 4)
void hx_fused(const float* __restrict__ yp, const int* __restrict__ s, int n,
              const float* __restrict__ p_a, const float* __restrict__ p_b,
              float* __restrict__ out) {
    __shared__ unsigned int sh[NWARPS][SLOTS];
    __shared__ float4 sy[STAGES][THREADS];
    __shared__ int4   sg[STAGES][THREADS];
    __shared__ unsigned int s_c1;
    __shared__ bool s_last;
    const int tid = threadIdx.x;
    const int warp = tid >> 5;

    for (int i = tid; i < NWARPS * SLOTS; i += THREADS)
        (&sh[0][0])[i] = 0u;
    if (tid == 0) s_c1 = 0u;
    __syncthreads();

    // int(20*pct) in Python is computed in double; f32 0.7f*20 = 13.99999976
    // would floor to 13, so snap up with an epsilon before truncation.
    const int a_bin = (int)floorf((float)BINS * __ldg(p_a) + 1e-4f);
    const int b_bin = (int)floorf((float)BINS * __ldg(p_b) + 1e-4f);
    const unsigned int lo   = (unsigned int)max(a_bin - 1, 0);
    const unsigned int hi   = (unsigned int)(min(b_bin, BINS) - 1);
    const unsigned int span = hi - lo;

    unsigned int* my = sh[warp];
    unsigned int c1 = 0;

    const int nvec = n >> 2;
    const float4* __restrict__ yp4 = (const float4*)yp;
    const int4*   __restrict__ s4p = (const int4*)s;
    const int T = gridDim.x * THREADS;
    const int base = blockIdx.x * THREADS + tid;
    // This thread's grid-stride iteration count.
    const int iters = (base < nvec) ? ((nvec - base - 1) / T + 1) : 0;

    uint32_t sy_a = (uint32_t)__cvta_generic_to_shared(&sy[0][tid]);
    uint32_t sg_a = (uint32_t)__cvta_generic_to_shared(&sg[0][tid]);
    const uint32_t stage_stride = THREADS * 16;   // bytes between stages

    // Prologue: fill up to STAGES stages. Commit unconditionally so every
    // thread's group count stays aligned.
    #pragma unroll
    for (int st = 0; st < STAGES; st++) {
        if (st < iters) {
            cpa16(sy_a + st * stage_stride, yp4 + base + st * T);
            cpa16(sg_a + st * stage_stride, s4p + base + st * T);
        }
        cpa_commit();
    }

    // Steady state: each thread consumes only the slot it filled (no block
    // sync needed). Consume BEFORE refilling the slot (reuse hazard).
    for (int it = 0; it < iters; it++) {
        cpa_wait<STAGES - 1>();           // stage `it` complete
        int st = it & (STAGES - 1);
        float4 x4 = sy[st][tid];
        int4   g4 = sg[st][tid];
        hx_accum(my, x4.x, g4.x, lo, span, c1);
        hx_accum(my, x4.y, g4.y, lo, span, c1);
        hx_accum(my, x4.z, g4.z, lo, span, c1);
        hx_accum(my, x4.w, g4.w, lo, span, c1);
        int nx = it + STAGES;
        if (nx < iters) {
            cpa16(sy_a + st * stage_stride, yp4 + base + nx * T);
            cpa16(sg_a + st * stage_stride, s4p + base + nx * T);
        }
        cpa_commit();
    }
    cpa_wait<0>();   // drain before smem slots are reused below (none) / exit

    // tail (n not divisible by 4)
    {
        int rem_base = nvec << 2;
        int gtid = base;   // blockIdx.x*THREADS + tid
        if (gtid < n - rem_base) {
            int idx = rem_base + gtid;
            hx_accum(my, yp[idx], s[idx], lo, span, c1);
        }
    }

    // Exact group-1 count: warp redux -> smem -> one global atomic per block.
    c1 = __reduce_add_sync(0xffffffffu, c1);
    if ((tid & 31) == 0 && c1) atomicAdd(&s_c1, c1);
    __syncthreads();

    // Reduce warp copies; ONE packed global atomic per slot per block.
    if (tid < SLOTS) {
        unsigned int cnt = 0, fr = 0;
        #pragma unroll
        for (int w = 0; w < NWARPS; w++) {
            unsigned int v = sh[w][tid];
            cnt += v >> CNT_SHIFT;
            fr  += v & ((1u << CNT_SHIFT) - 1u);
        }
        if (cnt) atomicAdd(&g_tot[tid], ((unsigned long long)cnt << TOT_SHIFT) | fr);
    }
    if (tid == 0) atomicAdd(&g_cnt1, s_c1);

    __threadfence();
    if (tid == 0) {
        unsigned int prev = atomicAdd(&g_done, 1u);
        s_last = (prev == gridDim.x - 1);
    }
    __syncthreads();
    if (!s_last) return;
    __threadfence();

    // ---- Last block: ~40 loads, compute loss, reset state ----
    if (tid == 0) {
        float cnt[2][BINS], fr[2][BINS];
        for (int g = 0; g < 2; g++) {
            for (int b = 0; b < BINS; b++) {
                unsigned long long v = g_tot[g * BINS + b];
                cnt[g][b] = (float)(v >> TOT_SHIFT);
                fr[g][b]  = (float)(v & ((1ULL << TOT_SHIFT) - 1ULL)) * INV_FRAC_SCALE;
            }
        }

        float W[2][NODES];
        for (int g = 0; g < 2; g++) {
            for (int k = 0; k < NODES; k++) {
                float w = 0.0f;
                if (k < BINS) w += cnt[g][k] - fr[g][k];
                if (k > 0)    w += fr[g][k - 1];
                W[g][k] = w;
            }
        }

        // Triangular weights per element sum to exactly 1, so the histogram
        // normalizers are just the group sizes.
        float S1 = (float)g_cnt1;
        float S0 = (float)n - S1;
        float inv0 = (S0 > 0.0f) ? 1.0f / S0 : 0.0f;
        float inv1 = (S1 > 0.0f) ? 1.0f / S1 : 0.0f;

        float loss = 0.0f;
        for (int k = 0; k < NODES; k++) {
            if (k >= a_bin && k < b_bin)
                loss += fabsf(W[0][k] * inv0 - W[1][k] * inv1);
        }
        out[0] = loss;
        g_done = 0u;
        g_cnt1 = 0u;
    }
    __syncthreads();
    if (tid < SLOTS) g_tot[tid] = 0ULL;   // reset for next graph replay
}

extern "C" void kernel_launch(void* const* d_in, const int* in_sizes, int n_in,
                              void* d_out, int out_size) {
    const float* y_pred = (const float*)d_in[0];
    const int*   s      = (const int*)d_in[1];
    // d_in[2] = y_gt (unused)
    const float* pct_a  = (const float*)d_in[3];
    const float* pct_b  = (const float*)d_in[4];
    float* out = (float*)d_out;
    int n = in_sizes[0];

    int nvec = n >> 2;
    int blocks = (nvec + THREADS - 1) / THREADS;
    if (blocks > MAXBLOCKS) blocks = MAXBLOCKS;   // 4 CTAs/SM x 148 SMs
    if (blocks < 1) blocks = 1;

    hx_fused<<<blocks, THREADS>>>(y_pred, s, n, pct_a, pct_b, out);
}

// round 11
// speedup vs baseline: 1.0393x; 1.0393x over previous
#include <cuda_runtime.h>
#include <cuda_bf16.h>
#include <cstdint>

#define BINS 20
#define NODES 21
#define NWARPS 8
#define THREADS 256
#define CTAS_PER_SM 3
#define MAXBLOCKS 444
#define SLOTS (2 * BINS)
#define FRAC_BITS 13
#define FRAC_MASK ((1u << FRAC_BITS) - 1u)
#define INV_FRAC_SCALE (1.0f/8192.0f)
#define CNT_SHIFT 20                /* smem u32 pack: cnt<<20 | frac13 */
#define PACK_SCALE 163840.0f        /* BINS << FRAC_BITS = 20*8192 */
#define MAGIC 12582912.0f           /* 1.5 * 2^23: float->fixed trick */
#define MAGIC_BITS 0x4B400000u
#define TOT_SHIFT 36                /* global u64 pack: cnt<<36 | frac_sum */

// Packed totals + group-1 count. Static-zero at load; last block re-zeroes
// every launch so graph replays are deterministic.
__device__ unsigned long long g_tot[SLOTS];
__device__ unsigned int g_cnt1;
__device__ unsigned int g_done;

__device__ __forceinline__ void hx_accum(unsigned int* my, float x, int g,
                                         unsigned int lo, unsigned int span,
                                         unsigned int& c1) {
    // Float->fixed via FFMA magic: t = x*163840 + 1.5*2^23 lands in the
    // [2^23,2^24) binade (ulp=1), so bits(t)-MAGIC_BITS == rn(x*163840).
    // RN vs floor only shifts boundary elements continuously between
    // adjacent nodes (triangular kernel is continuous) -> loss unchanged.
    unsigned int u = __float_as_uint(fmaf(x, PACK_SCALE, MAGIC)) - MAGIC_BITS;
    unsigned int k = u >> FRAC_BITS;
    c1 += (unsigned int)g;                                  // exact group count
    if (k - lo <= span) {   // single unsigned compare: lo <= k <= hi
        unsigned int pk = (u & FRAC_MASK) | (1u << CNT_SHIFT);
        atomicAdd(&my[g * BINS + k], pk);
    }
}

__global__ __launch_bounds__(THREADS, CTAS_PER_SM)
void hx_fused(const float* __restrict__ yp, const int* __restrict__ s, int n,
              const float* __restrict__ p_a, const float* __restrict__ p_b,
              float* __restrict__ out) {
    __shared__ unsigned int sh[NWARPS][SLOTS];
    __shared__ unsigned int s_c1;
    __shared__ bool s_last;
    const int tid = threadIdx.x;
    const int warp = tid >> 5;

    for (int i = tid; i < NWARPS * SLOTS; i += THREADS)
        (&sh[0][0])[i] = 0u;
    if (tid == 0) s_c1 = 0u;
    __syncthreads();

    // int(20*pct) in Python is computed in double; f32 0.7f*20 = 13.99999976
    // would floor to 13, so snap up with an epsilon before truncation.
    const int a_bin = (int)floorf((float)BINS * __ldg(p_a) + 1e-4f);
    const int b_bin = (int)floorf((float)BINS * __ldg(p_b) + 1e-4f);
    const unsigned int lo   = (unsigned int)max(a_bin - 1, 0);
    const unsigned int hi   = (unsigned int)(min(b_bin, BINS) - 1);
    const unsigned int span = hi - lo;

    unsigned int* my = sh[warp];
    unsigned int c1 = 0;

    const int nvec = n >> 2;
    const float4* __restrict__ yp4 = (const float4*)yp;
    const int4*   __restrict__ s4p = (const int4*)s;
    const int T = gridDim.x * THREADS;

    int i = blockIdx.x * THREADS + tid;
    // Main loop: 8 independent LDG.128 front-batched. At the 85-reg budget
    // (3 CTAs/SM) ptxas can keep all 8 loads in flight simultaneously.
    for (; i + 3 * T < nvec; i += 4 * T) {
        float4 xa = yp4[i];
        float4 xb = yp4[i + T];
        float4 xc = yp4[i + 2 * T];
        float4 xd = yp4[i + 3 * T];
        int4   ga = s4p[i];
        int4   gb = s4p[i + T];
        int4   gc = s4p[i + 2 * T];
        int4   gd = s4p[i + 3 * T];
        hx_accum(my, xa.x, ga.x, lo, span, c1);
        hx_accum(my, xa.y, ga.y, lo, span, c1);
        hx_accum(my, xa.z, ga.z, lo, span, c1);
        hx_accum(my, xa.w, ga.w, lo, span, c1);
        hx_accum(my, xb.x, gb.x, lo, span, c1);
        hx_accum(my, xb.y, gb.y, lo, span, c1);
        hx_accum(my, xb.z, gb.z, lo, span, c1);
        hx_accum(my, xb.w, gb.w, lo, span, c1);
        hx_accum(my, xc.x, gc.x, lo, span, c1);
        hx_accum(my, xc.y, gc.y, lo, span, c1);
        hx_accum(my, xc.z, gc.z, lo, span, c1);
        hx_accum(my, xc.w, gc.w, lo, span, c1);
        hx_accum(my, xd.x, gd.x, lo, span, c1);
        hx_accum(my, xd.y, gd.y, lo, span, c1);
        hx_accum(my, xd.z, gd.z, lo, span, c1);
        hx_accum(my, xd.w, gd.w, lo, span, c1);
    }
    for (; i < nvec; i += T) {
        float4 x4 = yp4[i];
        int4   g4 = s4p[i];
        hx_accum(my, x4.x, g4.x, lo, span, c1);
        hx_accum(my, x4.y, g4.y, lo, span, c1);
        hx_accum(my, x4.z, g4.z, lo, span, c1);
        hx_accum(my, x4.w, g4.w, lo, span, c1);
    }

    // tail (n not divisible by 4)
    {
        int rem_base = nvec << 2;
        int gtid = blockIdx.x * THREADS + tid;
        if (gtid < n - rem_base) {
            int idx = rem_base + gtid;
            hx_accum(my, yp[idx], s[idx], lo, span, c1);
        }
    }

    // Exact group-1 count: warp redux -> smem -> one global atomic per block.
    c1 = __reduce_add_sync(0xffffffffu, c1);
    if ((tid & 31) == 0 && c1) atomicAdd(&s_c1, c1);
    __syncthreads();

    // Reduce warp copies; ONE packed global atomic per slot per block.
    if (tid < SLOTS) {
        unsigned int cnt = 0, fr = 0;
        #pragma unroll
        for (int w = 0; w < NWARPS; w++) {
            unsigned int v = sh[w][tid];
            cnt += v >> CNT_SHIFT;
            fr  += v & ((1u << CNT_SHIFT) - 1u);
        }
        if (cnt) atomicAdd(&g_tot[tid], ((unsigned long long)cnt << TOT_SHIFT) | fr);
    }
    if (tid == 0) atomicAdd(&g_cnt1, s_c1);

    __threadfence();
    if (tid == 0) {
        unsigned int prev = atomicAdd(&g_done, 1u);
        s_last = (prev == gridDim.x - 1);
    }
    __syncthreads();
    if (!s_last) return;
    __threadfence();

    // ---- Last block: ~40 loads, compute loss, reset state ----
    if (tid == 0) {
        float cnt[2][BINS], fr[2][BINS];
        for (int g = 0; g < 2; g++) {
            for (int b = 0; b < BINS; b++) {
                unsigned long long v = g_tot[g * BINS + b];
                cnt[g][b] = (float)(v >> TOT_SHIFT);
                fr[g][b]  = (float)(v & ((1ULL << TOT_SHIFT) - 1ULL)) * INV_FRAC_SCALE;
            }
        }

        float W[2][NODES];
        for (int g = 0; g < 2; g++) {
            for (int k = 0; k < NODES; k++) {
                float w = 0.0f;
                if (k < BINS) w += cnt[g][k] - fr[g][k];
                if (k > 0)    w += fr[g][k - 1];
                W[g][k] = w;
            }
        }

        // Triangular weights per element sum to exactly 1, so the histogram
        // normalizers are just the group sizes.
        float S1 = (float)g_cnt1;
        float S0 = (float)n - S1;
        float inv0 = (S0 > 0.0f) ? 1.0f / S0 : 0.0f;
        float inv1 = (S1 > 0.0f) ? 1.0f / S1 : 0.0f;

        float loss = 0.0f;
        for (int k = 0; k < NODES; k++) {
            if (k >= a_bin && k < b_bin)
                loss += fabsf(W[0][k] * inv0 - W[1][k] * inv1);
        }
        out[0] = loss;
        g_done = 0u;
        g_cnt1 = 0u;
    }
    __syncthreads();
    if (tid < SLOTS) g_tot[tid] = 0ULL;   // reset for next graph replay
}

extern "C" void kernel_launch(void* const* d_in, const int* in_sizes, int n_in,
                              void* d_out, int out_size) {
    const float* y_pred = (const float*)d_in[0];
    const int*   s      = (const int*)d_in[1];
    // d_in[2] = y_gt (unused)
    const float* pct_a  = (const float*)d_in[3];
    const float* pct_b  = (const float*)d_in[4];
    float* out = (float*)d_out;
    int n = in_sizes[0];

    int nvec = n >> 2;
    int blocks = (nvec + THREADS - 1) / THREADS;
    if (blocks > MAXBLOCKS) blocks = MAXBLOCKS;   // 3 CTAs/SM x 148 SMs
    if (blocks < 1) blocks = 1;

    hx_fused<<<blocks, THREADS>>>(y_pred, s, n, pct_a, pct_b, out);
}